// round 1
// baseline (speedup 1.0000x reference)
#include <cuda_runtime.h>
#include <cuda_bf16.h>

// Problem constants (fixed by the reference: N=100000, E=1600000)
#define NMAX 100000

// Scratch (device globals — no allocation allowed in kernel_launch)
__device__ float g_a1[NMAX * 4];      // layer-1 aggregated raw features
__device__ float g_h2pre[NMAX * 32];  // h1 @ W2 (pre-aggregation features for layer 2)
__device__ float g_a2[NMAX * 32];     // layer-2 aggregated features
__device__ int   g_deg[NMAX];
__device__ float g_dinv[NMAX];

// ---------------------------------------------------------------------------
// red.global.add.v4.f32 helper (sm_90+): fire-and-forget vector atomic add
// ---------------------------------------------------------------------------
__device__ __forceinline__ void red_add_v4(float* p, float4 v) {
    asm volatile(
        "{\n\t"
        ".reg .u64 q;\n\t"
        "cvta.to.global.u64 q, %0;\n\t"
        "red.global.add.v4.f32 [q], {%1, %2, %3, %4};\n\t"
        "}"
        :: "l"(p), "f"(v.x), "f"(v.y), "f"(v.z), "f"(v.w)
        : "memory");
}

// ---------------------------------------------------------------------------
// K0: zero scratch accumulators
// ---------------------------------------------------------------------------
__global__ void k_zero(int n) {
    int i = blockIdx.x * blockDim.x + threadIdx.x;
    if (i < n * 32) g_a2[i] = 0.0f;
    if (i < n * 4)  g_a1[i] = 0.0f;
    if (i < n)      g_deg[i] = 0;
}

// ---------------------------------------------------------------------------
// K1: degree over dst (self-loop added later as +1)
// ---------------------------------------------------------------------------
__global__ void k_deg(const int* __restrict__ dst, int E) {
    int e = blockIdx.x * blockDim.x + threadIdx.x;
    if (e < E) atomicAdd(&g_deg[dst[e]], 1);
}

// ---------------------------------------------------------------------------
// K2: dinv = rsqrt(deg + 1)   (deg >= 1 always due to self-loops)
// ---------------------------------------------------------------------------
__global__ void k_dinv(int n) {
    int i = blockIdx.x * blockDim.x + threadIdx.x;
    if (i < n) g_dinv[i] = rsqrtf((float)(g_deg[i] + 1));
}

// ---------------------------------------------------------------------------
// K3: layer-1 scatter of RAW features (aggregation commutes with W1):
//     a1[d] += x[s] * dinv[s] * dinv[d]      (one thread per edge, red.v4)
// ---------------------------------------------------------------------------
__global__ void k_scatter1(const float4* __restrict__ x4,
                           const int* __restrict__ src,
                           const int* __restrict__ dst, int E) {
    int e = blockIdx.x * blockDim.x + threadIdx.x;
    if (e >= E) return;
    int s = src[e], d = dst[e];
    float norm = g_dinv[s] * g_dinv[d];
    float4 v = x4[s];
    v.x *= norm; v.y *= norm; v.z *= norm; v.w *= norm;
    red_add_v4(&g_a1[d * 4], v);
}

// ---------------------------------------------------------------------------
// K4: per node:  v = a1 + x*dinv^2  (add self-loop message)
//     h1 = relu(v @ W1 + b1)        [64]
//     h2pre = h1 @ W2               [32]   (pre-transform for layer 2)
//     one thread per node; weights staged in shared memory
// ---------------------------------------------------------------------------
__global__ void k_layer1(const float4* __restrict__ x4,
                         const float* __restrict__ W1,   // [4,64]
                         const float* __restrict__ b1,   // [64]
                         const float* __restrict__ W2,   // [64,32]
                         int n) {
    __shared__ float sW1[4 * 64];
    __shared__ float sb1[64];
    __shared__ float sW2[64 * 32];
    int t = threadIdx.x;
    for (int i = t; i < 256; i += blockDim.x)  sW1[i] = W1[i];
    for (int i = t; i < 64;  i += blockDim.x)  sb1[i] = b1[i];
    for (int i = t; i < 2048; i += blockDim.x) sW2[i] = W2[i];
    __syncthreads();

    int i = blockIdx.x * blockDim.x + t;
    if (i >= n) return;

    float di = g_dinv[i];
    float s2 = di * di;
    float4 a  = *(const float4*)&g_a1[i * 4];
    float4 xv = x4[i];
    float v0 = a.x + xv.x * s2;
    float v1 = a.y + xv.y * s2;
    float v2 = a.z + xv.z * s2;
    float v3 = a.w + xv.w * s2;

    float acc[32];
#pragma unroll
    for (int j = 0; j < 32; j++) acc[j] = 0.0f;

#pragma unroll 8
    for (int f = 0; f < 64; f++) {
        float h = fmaf(v0, sW1[f],
                  fmaf(v1, sW1[64 + f],
                  fmaf(v2, sW1[128 + f],
                  fmaf(v3, sW1[192 + f], sb1[f]))));
        h = fmaxf(h, 0.0f);
        const float4* w2row = (const float4*)&sW2[f * 32];
#pragma unroll
        for (int j = 0; j < 8; j++) {
            float4 w = w2row[j];
            acc[4 * j + 0] = fmaf(h, w.x, acc[4 * j + 0]);
            acc[4 * j + 1] = fmaf(h, w.y, acc[4 * j + 1]);
            acc[4 * j + 2] = fmaf(h, w.z, acc[4 * j + 2]);
            acc[4 * j + 3] = fmaf(h, w.w, acc[4 * j + 3]);
        }
    }

    float4* o = (float4*)&g_h2pre[i * 32];
#pragma unroll
    for (int j = 0; j < 8; j++)
        o[j] = make_float4(acc[4 * j], acc[4 * j + 1], acc[4 * j + 2], acc[4 * j + 3]);
}

// ---------------------------------------------------------------------------
// K5: layer-2 scatter:  a2[d] += h2pre[s] * dinv[s]*dinv[d]
//     8 threads per edge, each handles one float4 (coalesced gather + red.v4)
// ---------------------------------------------------------------------------
__global__ void k_scatter2(const int* __restrict__ src,
                           const int* __restrict__ dst, int E) {
    int gid = blockIdx.x * blockDim.x + threadIdx.x;
    int e = gid >> 3;
    int c = gid & 7;
    if (e >= E) return;
    int s = src[e], d = dst[e];
    float norm = g_dinv[s] * g_dinv[d];
    float4 v = *(const float4*)&g_h2pre[s * 32 + c * 4];
    v.x *= norm; v.y *= norm; v.z *= norm; v.w *= norm;
    red_add_v4(&g_a2[d * 32 + c * 4], v);
}

// ---------------------------------------------------------------------------
// K6: finalize:  h2 = relu(a2 + h2pre*dinv^2 + b2)
//                out = relu(h2 @ Wf + bf)
//     one warp per node, lane = output feature; h2 staged in shared
// ---------------------------------------------------------------------------
__global__ void k_final(const float* __restrict__ b2,   // [32]
                        const float* __restrict__ Wf,   // [32,32]
                        const float* __restrict__ bf,   // [32]
                        float* __restrict__ out, int n) {
    __shared__ float sWf[32 * 32];
    __shared__ float sbf[32];
    __shared__ float sb2[32];
    __shared__ float sh[8][33];  // 8 nodes per 256-thread block, padded
    int t = threadIdx.x;
    for (int i = t; i < 1024; i += blockDim.x) sWf[i] = Wf[i];
    if (t < 32) { sbf[t] = bf[t]; sb2[t] = b2[t]; }
    __syncthreads();

    int w = t >> 5;
    int j = t & 31;
    int node = blockIdx.x * 8 + w;
    if (node >= n) return;

    float di = g_dinv[node];
    float s2 = di * di;
    float h = g_a2[node * 32 + j] + g_h2pre[node * 32 + j] * s2 + sb2[j];
    h = fmaxf(h, 0.0f);
    sh[w][j] = h;
    __syncwarp();

    float acc = sbf[j];
#pragma unroll
    for (int k = 0; k < 32; k++)
        acc = fmaf(sh[w][k], sWf[k * 32 + j], acc);
    out[node * 32 + j] = fmaxf(acc, 0.0f);
}

// ---------------------------------------------------------------------------
// Launch
// Inputs (metadata order): x[N,4], edge_index[2,E], W1[4,64], b1[64],
//                          W2[64,32], b2[32], Wf[32,32], bf[32]
// Output: [N,32] float32
// ---------------------------------------------------------------------------
extern "C" void kernel_launch(void* const* d_in, const int* in_sizes, int n_in,
                              void* d_out, int out_size) {
    const float* x   = (const float*)d_in[0];
    const int*   ei  = (const int*)d_in[1];
    const float* W1  = (const float*)d_in[2];
    const float* b1  = (const float*)d_in[3];
    const float* W2  = (const float*)d_in[4];
    const float* b2  = (const float*)d_in[5];
    const float* Wf  = (const float*)d_in[6];
    const float* bf  = (const float*)d_in[7];
    float* out = (float*)d_out;

    int n = in_sizes[0] / 4;
    int E = in_sizes[1] / 2;
    const int* src = ei;
    const int* dst = ei + E;

    const int T = 256;

    k_zero<<<(n * 32 + T - 1) / T, T>>>(n);
    k_deg<<<(E + T - 1) / T, T>>>(dst, E);
    k_dinv<<<(n + T - 1) / T, T>>>(n);
    k_scatter1<<<(E + T - 1) / T, T>>>((const float4*)x, src, dst, E);
    k_layer1<<<(n + T - 1) / T, T>>>((const float4*)x, W1, b1, W2, n);
    k_scatter2<<<(E * 8 + T - 1) / T, T>>>(src, dst, E);
    k_final<<<(n + 7) / 8, T>>>(b2, Wf, bf, out, n);
}